// round 10
// baseline (speedup 1.0000x reference)
#include <cuda_runtime.h>
#include <cuda_fp16.h>

#define Bsz 4
#define S   2048
#define D   128
#define H   8
#define DK  16
#define BH  (Bsz*H)

typedef unsigned long long u64;
typedef unsigned int u32;

// 0.25 * log2(e): folded into Q at projection time so attention uses raw ex2
#define SCQ 0.36067376022224086f

// ---- scratch (no device allocations allowed) ----
__device__ float g_Q[BH*S*DK];                // pre-scaled by SCQ
__device__ float g_K[BH*S*DK];
__device__ float g_V[BH*S*DK];
__device__ float g_Vp[BH*S*DK];               // V * rcs (normalized V)
__device__ __half g_E[(size_t)BH*S*S];        // 256 MB, [bh][m][q], per-column biased
__device__ float g_bias[BH*S];                // CS column bias b_m
__device__ float g_maxqn[BH];                 // max ||Qhat|| per head
__device__ float g_head[Bsz*S*D];

// ---- packed fp32x2 helpers ----
__device__ __forceinline__ void ffma2(u64& d, u64 a, u64 b){
    asm("fma.rn.f32x2 %0, %1, %2, %0;" : "+l"(d) : "l"(a), "l"(b));
}
__device__ __forceinline__ u64 add2(u64 a, u64 b){
    u64 r; asm("add.rn.f32x2 %0, %1, %2;" : "=l"(r) : "l"(a), "l"(b)); return r;
}
__device__ __forceinline__ u64 pack2(float lo, float hi){
    u64 r; asm("mov.b64 %0, {%1, %2};" : "=l"(r) : "f"(lo), "f"(hi)); return r;
}
__device__ __forceinline__ u64 dup2(float x){
    u64 r; asm("mov.b64 %0, {%1, %1};" : "=l"(r) : "f"(x)); return r;
}
__device__ __forceinline__ float hsum2(u64 v){
    float lo, hi; asm("mov.b64 {%0, %1}, %2;" : "=f"(lo), "=f"(hi) : "l"(v));
    return lo + hi;
}
__device__ __forceinline__ float2 unpk(u64 v){
    float2 r; asm("mov.b64 {%0, %1}, %2;" : "=f"(r.x), "=f"(r.y) : "l"(v));
    return r;
}
__device__ __forceinline__ float ex2f(float x){
    float r; asm("ex2.approx.f32 %0, %1;" : "=f"(r) : "f"(x)); return r;
}
__device__ __forceinline__ u64 lds64(const float* p){
    return *reinterpret_cast<const u64*>(p);
}
__device__ __forceinline__ u64 ldg64(const float* p){
    return *reinterpret_cast<const u64*>(p);
}

// ============================================================
// Kernel 1: Q/K/V projections. grid (B*S/64, 3), 128 threads.
// ============================================================
__global__ void proj_kernel(const float* __restrict__ x,
                            const float* __restrict__ wq,
                            const float* __restrict__ wk,
                            const float* __restrict__ wv) {
    __shared__ float xs[64][132];
    __shared__ float wsT[16][132];
    const int t = threadIdx.x;       // 128
    const int row0 = blockIdx.x * 64;
    const int pj = blockIdx.y;
    const float* W0 = (pj == 0 ? wq : pj == 1 ? wk : wv);
    float* dst = (pj == 0 ? g_Q : pj == 1 ? g_K : g_V);
    const float oscale = (pj == 0) ? SCQ : 1.0f;

    #pragma unroll
    for (int k = 0; k < 16; k++) {
        int idx = t + k*128;
        int r = idx >> 5, q4 = idx & 31;
        *reinterpret_cast<float4*>(&xs[r][q4*4]) =
            *reinterpret_cast<const float4*>(x + (row0 + r)*D + q4*4);
    }

    const int rg = t >> 3, cg = t & 7;
    for (int h = 0; h < H; h++) {
        __syncthreads();
        #pragma unroll
        for (int k = 0; k < 4; k++) {
            int idx = t + k*128;
            int d = idx >> 2, c4 = idx & 3;
            float4 v = *reinterpret_cast<const float4*>(W0 + h*D*DK + d*DK + c4*4);
            wsT[c4*4+0][d] = v.x; wsT[c4*4+1][d] = v.y;
            wsT[c4*4+2][d] = v.z; wsT[c4*4+3][d] = v.w;
        }
        __syncthreads();

        u64 acc[4][2] = {};
        #pragma unroll 8
        for (int d = 0; d < D; d += 2) {
            u64 w0 = lds64(&wsT[cg][d]);
            u64 w1 = lds64(&wsT[cg+8][d]);
            #pragma unroll
            for (int i = 0; i < 4; i++) {
                u64 xv = lds64(&xs[rg*4+i][d]);
                ffma2(acc[i][0], xv, w0);
                ffma2(acc[i][1], xv, w1);
            }
        }
        #pragma unroll
        for (int i = 0; i < 4; i++) {
            int grow = row0 + rg*4 + i;
            int b = grow >> 11, s = grow & (S-1);
            float* o = dst + ((b*H + h)*S + s)*DK;
            o[cg]   = hsum2(acc[i][0]) * oscale;
            o[cg+8] = hsum2(acc[i][1]) * oscale;
        }
    }
}

// ============================================================
// Kernel 1b: maxQnorm[bh] = max_q ||Qhat[q]||. grid BH, 256 threads.
// ============================================================
__global__ void __launch_bounds__(256) qnorm_kernel() {
    __shared__ float red[256];
    const int bh = blockIdx.x, t = threadIdx.x;
    const float* Qb = g_Q + bh*S*DK;
    float mx = 0.f;
    for (int r = t; r < S; r += 256) {
        u64 a = 0;
        #pragma unroll
        for (int j = 0; j < 8; j++) {
            u64 q = ldg64(Qb + r*DK + 2*j);
            ffma2(a, q, q);
        }
        mx = fmaxf(mx, hsum2(a));
    }
    red[t] = mx;
    __syncthreads();
    #pragma unroll
    for (int s2 = 128; s2; s2 >>= 1) {
        if (t < s2) red[t] = fmaxf(red[t], red[t + s2]);
        __syncthreads();
    }
    if (t == 0) g_maxqn[bh] = sqrtf(red[0]);
}

// ============================================================
// Kernel 1c: bias[m] = maxQn*||K[m]|| - 8 (Cauchy-Schwarz bound).
// grid BH*S/256, 256 threads, 1 row each.
// ============================================================
__global__ void __launch_bounds__(256) kbias_kernel() {
    const int row = blockIdx.x*256 + threadIdx.x;   // [0, BH*S)
    const float* Kr = g_K + row*DK;
    u64 a = 0;
    #pragma unroll
    for (int j = 0; j < 8; j++) {
        u64 k = ldg64(Kr + 2*j);
        ffma2(a, k, k);
    }
    g_bias[row] = fmaf(sqrtf(hsum2(a)), g_maxqn[row >> 11], -8.0f);
}

// ============================================================
// Kernel 2: E[m][q] = 2^(Qhat[q].K[m] - b_m) fp16.
// grid (S/64, BH), 128 threads, NO smem, NO barriers.
// Lane = q-pair (Q in regs). Warp w streams m in [512w, 512w+512):
// per m: warp-uniform K-row loads (L1-hot) + coalesced 128B E store.
// Overflow impossible by the CS bound (E <= 2^8).
// ============================================================
__global__ void __launch_bounds__(128) scoresE_kernel() {
    const int t = threadIdx.x, w = t >> 5, lane = t & 31;
    const int bh = blockIdx.y;
    const int q0 = blockIdx.x * 64;
    const float* Qb = g_Q + (bh*S + q0)*DK;
    const float* Kb = g_K + bh*S*DK;
    const float* Bb = g_bias + bh*S;
    __half* Eb = g_E + (size_t)bh*S*S;

    u64 qa[8], qc[8];
    #pragma unroll
    for (int j = 0; j < 8; j++) {
        qa[j] = ldg64(Qb + (2*lane)*DK + 2*j);
        qc[j] = ldg64(Qb + (2*lane + 1)*DK + 2*j);
    }

    const int m0 = w * 512;
    #pragma unroll 4
    for (int i = 0; i < 512; i++) {
        const int m = m0 + i;
        const ulonglong2* kp = reinterpret_cast<const ulonglong2*>(Kb + m*DK);
        const u64 bias = pack2(-Bb[m], 0.0f);
        ulonglong2 kv0 = kp[0], kv1 = kp[1];     // uniform LDG.128 (broadcast)
        ulonglong2 kv2 = kp[2], kv3 = kp[3];
        u64 a0 = bias, a1 = 0, a2 = bias, a3 = 0;
        ffma2(a0, qa[0], kv0.x); ffma2(a1, qa[1], kv0.y);
        ffma2(a2, qc[0], kv0.x); ffma2(a3, qc[1], kv0.y);
        ffma2(a0, qa[2], kv1.x); ffma2(a1, qa[3], kv1.y);
        ffma2(a2, qc[2], kv1.x); ffma2(a3, qc[3], kv1.y);
        ffma2(a0, qa[4], kv2.x); ffma2(a1, qa[5], kv2.y);
        ffma2(a2, qc[4], kv2.x); ffma2(a3, qc[5], kv2.y);
        ffma2(a0, qa[6], kv3.x); ffma2(a1, qa[7], kv3.y);
        ffma2(a2, qc[6], kv3.x); ffma2(a3, qc[7], kv3.y);
        float e0 = ex2f(hsum2(add2(a0, a1)));    // bound guarantees <= 2^8
        float e1 = ex2f(hsum2(add2(a2, a3)));
        *reinterpret_cast<__half2*>(Eb + (size_t)m*S + q0 + 2*lane) =
            __floats2half2_rn(e0, e1);           // coalesced 128B/warp
    }
}

// ============================================================
// Kernel 2b: colsum of stored E rows + write Vp = V/colsum.
// One warp per m-row, coalesced uint4 loads. grid BH*S/8, 256 thr.
// rcs never hits memory -- folded straight into Vp.
// ============================================================
__global__ void __launch_bounds__(256) colsumVp_kernel() {
    const int w = threadIdx.x >> 5, lane = threadIdx.x & 31;
    const size_t row = (size_t)blockIdx.x*8 + w;       // [0, BH*S)
    const __half* Er = g_E + row*S;
    float s = 0.f;
    #pragma unroll
    for (int i = 0; i < 8; i++) {
        uint4 u = *reinterpret_cast<const uint4*>(Er + i*256 + lane*8);
        float2 f0 = __half22float2(*reinterpret_cast<__half2*>(&u.x));
        float2 f1 = __half22float2(*reinterpret_cast<__half2*>(&u.y));
        float2 f2 = __half22float2(*reinterpret_cast<__half2*>(&u.z));
        float2 f3 = __half22float2(*reinterpret_cast<__half2*>(&u.w));
        s += (f0.x + f0.y) + (f1.x + f1.y) + (f2.x + f2.y) + (f3.x + f3.y);
    }
    #pragma unroll
    for (int off = 16; off; off >>= 1)
        s += __shfl_xor_sync(0xffffffffu, s, off);
    const float rc = __frcp_rn(s);                     // all lanes have s
    if (lane < 8) {
        float2 v = unpk(ldg64(g_V + row*DK + 2*lane));
        *reinterpret_cast<u64*>(g_Vp + row*DK + 2*lane) =
            pack2(v.x * rc, v.y * rc);
    }
}

// ============================================================
// Kernel 3: out[q,:] = sum_m E[m][q] * Vp[m,:].
// grid (S/64, BH), 128 threads, NO smem staging, NO mid-loop barriers.
// Lane = q-pair; warp w streams m in [512w, 512w+512): 1 coalesced
// E load + 4 uniform Vp loads (L1-hot) + 16 FFMA2 per m.
// Single cross-warp reduction at the end.
// ============================================================
__global__ void __launch_bounds__(128) ev_kernel() {
    __shared__ float red[3][64][18];
    const int t = threadIdx.x, w = t >> 5, lane = t & 31;
    const int bh = blockIdx.y;
    const int q0 = blockIdx.x * 64;
    const float* Vp = g_Vp + bh*S*DK;
    const __half* Eb = g_E + (size_t)bh*S*S;

    u64 acc0[8] = {}, acc1[8] = {};

    const int m0 = w * 512;
    #pragma unroll 4
    for (int i = 0; i < 512; i++) {
        const int m = m0 + i;
        __half2 eh = *reinterpret_cast<const __half2*>(
            Eb + (size_t)m*S + q0 + 2*lane);           // coalesced 128B/warp
        const ulonglong2* vp = reinterpret_cast<const ulonglong2*>(Vp + m*DK);
        ulonglong2 v0 = vp[0], v1 = vp[1];             // uniform LDG.128
        ulonglong2 v2 = vp[2], v3 = vp[3];
        float2 ef = __half22float2(eh);
        u64 E0 = dup2(ef.x), E1 = dup2(ef.y);
        ffma2(acc0[0], E0, v0.x); ffma2(acc0[1], E0, v0.y);
        ffma2(acc1[0], E1, v0.x); ffma2(acc1[1], E1, v0.y);
        ffma2(acc0[2], E0, v1.x); ffma2(acc0[3], E0, v1.y);
        ffma2(acc1[2], E1, v1.x); ffma2(acc1[3], E1, v1.y);
        ffma2(acc0[4], E0, v2.x); ffma2(acc0[5], E0, v2.y);
        ffma2(acc1[4], E1, v2.x); ffma2(acc1[5], E1, v2.y);
        ffma2(acc0[6], E0, v3.x); ffma2(acc0[7], E0, v3.y);
        ffma2(acc1[6], E1, v3.x); ffma2(acc1[7], E1, v3.y);
    }

    // cross-warp reduction over the 4 m-slices
    __syncthreads();
    if (w) {
        #pragma unroll
        for (int j = 0; j < 8; j++) {
            float2 p0 = unpk(acc0[j]), p1 = unpk(acc1[j]);
            red[w-1][2*lane][2*j]       = p0.x;
            red[w-1][2*lane][2*j+1]     = p0.y;
            red[w-1][2*lane+1][2*j]     = p1.x;
            red[w-1][2*lane+1][2*j+1]   = p1.y;
        }
    }
    __syncthreads();
    if (w == 0) {
        const int b = bh >> 3, h = bh & 7;
        float o0[16], o1[16];
        #pragma unroll
        for (int j = 0; j < 8; j++) {
            float2 p0 = unpk(acc0[j]), p1 = unpk(acc1[j]);
            o0[2*j] = p0.x; o0[2*j+1] = p0.y;
            o1[2*j] = p1.x; o1[2*j+1] = p1.y;
        }
        #pragma unroll
        for (int sl = 0; sl < 3; sl++)
            #pragma unroll
            for (int c = 0; c < 16; c++) {
                o0[c] += red[sl][2*lane][c];
                o1[c] += red[sl][2*lane+1][c];
            }
        float* d0 = g_head + (b*S + q0 + 2*lane)*D     + h*DK;
        float* d1 = g_head + (b*S + q0 + 2*lane + 1)*D + h*DK;
        #pragma unroll
        for (int c4 = 0; c4 < 4; c4++) {
            *reinterpret_cast<float4*>(d0 + c4*4) =
                make_float4(o0[c4*4], o0[c4*4+1], o0[c4*4+2], o0[c4*4+3]);
            *reinterpret_cast<float4*>(d1 + c4*4) =
                make_float4(o1[c4*4], o1[c4*4+1], o1[c4*4+2], o1[c4*4+3]);
        }
    }
}

// ============================================================
// Kernel 4: out = head[B*S,128] @ w_o[128,128]. grid 256, 256 thr.
// ============================================================
__global__ void final_proj_kernel(const float* __restrict__ wo,
                                  float* __restrict__ out) {
    __shared__ float hsT[128][34];
    const int t = threadIdx.x;
    const int row0 = blockIdx.x * 32;

    #pragma unroll
    for (int k = 0; k < 4; k++) {
        int idx = t + k*256;
        int r = idx >> 5, j4 = idx & 31;
        float4 v = *reinterpret_cast<const float4*>(g_head + (row0 + r)*D + j4*4);
        hsT[j4*4+0][r] = v.x; hsT[j4*4+1][r] = v.y;
        hsT[j4*4+2][r] = v.z; hsT[j4*4+3][r] = v.w;
    }
    __syncthreads();

    const int c = t & 127, rh = t >> 7;
    u64 acc[8] = {};
    #pragma unroll 4
    for (int j = 0; j < D; j++) {
        u64 w = dup2(wo[j*D + c]);
        #pragma unroll
        for (int p = 0; p < 8; p++)
            ffma2(acc[p], lds64(&hsT[j][rh*16 + 2*p]), w);
    }
    #pragma unroll
    for (int p = 0; p < 8; p++) {
        float2 v = unpk(acc[p]);
        int r = row0 + rh*16 + 2*p;
        out[r*D + c]     = v.x;
        out[(r+1)*D + c] = v.y;
    }
}

// ============================================================
extern "C" void kernel_launch(void* const* d_in, const int* in_sizes, int n_in,
                              void* d_out, int out_size) {
    const float* x  = (const float*)d_in[0];
    const float* wq = (const float*)d_in[1];
    const float* wk = (const float*)d_in[2];
    const float* wv = (const float*)d_in[3];
    const float* wo = (const float*)d_in[4];
    float* out = (float*)d_out;

    proj_kernel      <<< dim3(Bsz*S/64, 3), 128 >>>(x, wq, wk, wv);
    qnorm_kernel     <<< BH,                256 >>>();
    kbias_kernel     <<< BH*S/256,          256 >>>();
    scoresE_kernel   <<< dim3(S/64, BH),    128 >>>();
    colsumVp_kernel  <<< BH*S/8,            256 >>>();
    ev_kernel        <<< dim3(S/64, BH),    128 >>>();
    final_proj_kernel<<< Bsz*S/32,          256 >>>(wo, out);
}

// round 12
// speedup vs baseline: 1.1465x; 1.1465x over previous
#include <cuda_runtime.h>
#include <cuda_fp16.h>

#define Bsz 4
#define S   2048
#define D   128
#define H   8
#define DK  16
#define BH  (Bsz*H)

typedef unsigned long long u64;
typedef unsigned int u32;

// 0.25 * log2(e): folded into Q at projection time so attention uses raw ex2
#define SCQ 0.36067376022224086f

// ---- scratch (no device allocations allowed) ----
__device__ float g_Q[BH*S*DK];                // pre-scaled by SCQ
__device__ float g_K[BH*S*DK];
__device__ float g_V[BH*S*DK];
__device__ __half g_E[(size_t)BH*S*S];        // 256 MB, [bh][m][q], per-column biased
__device__ __half g_VTa[BH*DK*S];             // bucketed (V*rc*2^10)^T, |.|<2^14
__device__ __half g_VTb[BH*DK*S];             // [2^14,2^29) stored *2^-15
__device__ __half g_VTc[BH*DK*S];             // >=2^29 stored *2^-30
__device__ float g_maxqn[BH];                 // max ||Qhat|| per head
__device__ float g_head[Bsz*S*D];

// ---- packed fp32x2 helpers ----
__device__ __forceinline__ void ffma2(u64& d, u64 a, u64 b){
    asm("fma.rn.f32x2 %0, %1, %2, %0;" : "+l"(d) : "l"(a), "l"(b));
}
__device__ __forceinline__ u64 add2(u64 a, u64 b){
    u64 r; asm("add.rn.f32x2 %0, %1, %2;" : "=l"(r) : "l"(a), "l"(b)); return r;
}
__device__ __forceinline__ u64 pack2(float lo, float hi){
    u64 r; asm("mov.b64 %0, {%1, %2};" : "=l"(r) : "f"(lo), "f"(hi)); return r;
}
__device__ __forceinline__ u64 dup2(float x){
    u64 r; asm("mov.b64 %0, {%1, %1};" : "=l"(r) : "f"(x)); return r;
}
__device__ __forceinline__ float hsum2(u64 v){
    float lo, hi; asm("mov.b64 {%0, %1}, %2;" : "=f"(lo), "=f"(hi) : "l"(v));
    return lo + hi;
}
__device__ __forceinline__ float2 unpk(u64 v){
    float2 r; asm("mov.b64 {%0, %1}, %2;" : "=f"(r.x), "=f"(r.y) : "l"(v));
    return r;
}
__device__ __forceinline__ float ex2f(float x){
    float r; asm("ex2.approx.f32 %0, %1;" : "=f"(r) : "f"(x)); return r;
}
__device__ __forceinline__ u64 lds64(const float* p){
    return *reinterpret_cast<const u64*>(p);
}
__device__ __forceinline__ u64 ldg64(const float* p){
    return *reinterpret_cast<const u64*>(p);
}
__device__ __forceinline__ u32 smem_u32(const void* p){
    u32 a;
    asm("{ .reg .u64 t; cvta.to.shared.u64 t, %1; cvt.u32.u64 %0, t; }"
        : "=r"(a) : "l"(p));
    return a;
}

// ============================================================
// Kernel 1: Q/K/V projections. grid (B*S/64, 3), 128 threads.
// ============================================================
__global__ void proj_kernel(const float* __restrict__ x,
                            const float* __restrict__ wq,
                            const float* __restrict__ wk,
                            const float* __restrict__ wv) {
    __shared__ float xs[64][132];
    __shared__ float wsT[16][132];
    const int t = threadIdx.x;       // 128
    const int row0 = blockIdx.x * 64;
    const int pj = blockIdx.y;
    const float* W0 = (pj == 0 ? wq : pj == 1 ? wk : wv);
    float* dst = (pj == 0 ? g_Q : pj == 1 ? g_K : g_V);
    const float oscale = (pj == 0) ? SCQ : 1.0f;

    #pragma unroll
    for (int k = 0; k < 16; k++) {
        int idx = t + k*128;
        int r = idx >> 5, q4 = idx & 31;
        *reinterpret_cast<float4*>(&xs[r][q4*4]) =
            *reinterpret_cast<const float4*>(x + (row0 + r)*D + q4*4);
    }

    const int rg = t >> 3, cg = t & 7;
    for (int h = 0; h < H; h++) {
        __syncthreads();
        #pragma unroll
        for (int k = 0; k < 4; k++) {
            int idx = t + k*128;
            int d = idx >> 2, c4 = idx & 3;
            float4 v = *reinterpret_cast<const float4*>(W0 + h*D*DK + d*DK + c4*4);
            wsT[c4*4+0][d] = v.x; wsT[c4*4+1][d] = v.y;
            wsT[c4*4+2][d] = v.z; wsT[c4*4+3][d] = v.w;
        }
        __syncthreads();

        u64 acc[4][2] = {};
        #pragma unroll 8
        for (int d = 0; d < D; d += 2) {
            u64 w0 = lds64(&wsT[cg][d]);
            u64 w1 = lds64(&wsT[cg+8][d]);
            #pragma unroll
            for (int i = 0; i < 4; i++) {
                u64 xv = lds64(&xs[rg*4+i][d]);
                ffma2(acc[i][0], xv, w0);
                ffma2(acc[i][1], xv, w1);
            }
        }
        #pragma unroll
        for (int i = 0; i < 4; i++) {
            int grow = row0 + rg*4 + i;
            int b = grow >> 11, s = grow & (S-1);
            float* o = dst + ((b*H + h)*S + s)*DK;
            o[cg]   = hsum2(acc[i][0]) * oscale;
            o[cg+8] = hsum2(acc[i][1]) * oscale;
        }
    }
}

// ============================================================
// Kernel 1b: maxQnorm[bh] = max_q ||Qhat[q]||. grid BH, 256 threads.
// ============================================================
__global__ void __launch_bounds__(256) qnorm_kernel() {
    __shared__ float red[256];
    const int bh = blockIdx.x, t = threadIdx.x;
    const float* Qb = g_Q + bh*S*DK;
    float mx = 0.f;
    for (int r = t; r < S; r += 256) {
        u64 a = 0;
        #pragma unroll
        for (int j = 0; j < 8; j++) {
            u64 q = ldg64(Qb + r*DK + 2*j);
            ffma2(a, q, q);
        }
        mx = fmaxf(mx, hsum2(a));
    }
    red[t] = mx;
    __syncthreads();
    #pragma unroll
    for (int s2 = 128; s2; s2 >>= 1) {
        if (t < s2) red[t] = fmaxf(red[t], red[t + s2]);
        __syncthreads();
    }
    if (t == 0) g_maxqn[bh] = sqrtf(red[0]);
}

// ============================================================
// Kernel 2: E[m][q] = 2^(Qhat[q].K[m] - b_m) fp16 with CS bias
// b_m = maxQn*||K[m]|| - 8 (overflow impossible). R9-proven shape:
// SMEM-staged K, per-chunk bias in smem, coalesced 128B stores.
// grid (S/64, BH), 128 threads; lane = q-pair, warps split m.
// ============================================================
__global__ void __launch_bounds__(128) scoresE_kernel() {
    __shared__ float Ks[128][16];
    __shared__ float bs[128];
    const int t = threadIdx.x, w = t >> 5, lane = t & 31;
    const int bh = blockIdx.y;
    const int q0 = blockIdx.x * 64;
    const float* Qb = g_Q + bh*S*DK;
    const float* Kb = g_K + bh*S*DK;
    __half* Eb = g_E + (size_t)bh*S*S;
    const float mq = g_maxqn[bh];

    u64 qa[8], qc[8];
    #pragma unroll
    for (int j = 0; j < 8; j++) {
        qa[j] = ldg64(Qb + (q0 + 2*lane)*DK + 2*j);
        qc[j] = ldg64(Qb + (q0 + 2*lane + 1)*DK + 2*j);
    }

    for (int m0 = 0; m0 < S; m0 += 128) {
        __syncthreads();                       // Ks/bs reuse
        #pragma unroll
        for (int i = 0; i < 4; i++) {
            int idx = t + i*128;
            int r = idx >> 2, c4 = idx & 3;
            *reinterpret_cast<float4*>(&Ks[r][c4*4]) =
                *reinterpret_cast<const float4*>(Kb + (m0 + r)*DK + c4*4);
        }
        __syncthreads();
        {   // per-row CS bias from SMEM (1 row per thread)
            const ulonglong2* kp = reinterpret_cast<const ulonglong2*>(&Ks[t][0]);
            u64 a = 0;
            #pragma unroll
            for (int p = 0; p < 4; p++) {
                ulonglong2 kv = kp[p];
                ffma2(a, kv.x, kv.x);
                ffma2(a, kv.y, kv.y);
            }
            bs[t] = fmaf(sqrtf(hsum2(a)), mq, -8.0f);
        }
        __syncthreads();

        const int mbase = w * 32;
        #pragma unroll 4
        for (int mi = 0; mi < 32; mi++) {
            const int m  = mbase + mi;
            const int mg = m0 + m;
            const u64 bias = pack2(-bs[m], 0.0f);
            const ulonglong2* kp = reinterpret_cast<const ulonglong2*>(&Ks[m][0]);
            u64 a0 = bias, a1 = 0, a2 = bias, a3 = 0;
            #pragma unroll
            for (int p = 0; p < 4; p++) {
                ulonglong2 kv = kp[p];               // LDS.128 broadcast
                ffma2(a0, qa[2*p],   kv.x);
                ffma2(a1, qa[2*p+1], kv.y);
                ffma2(a2, qc[2*p],   kv.x);
                ffma2(a3, qc[2*p+1], kv.y);
            }
            float e0 = fminf(ex2f(hsum2(add2(a0, a1))), 65472.0f);
            float e1 = fminf(ex2f(hsum2(add2(a2, a3))), 65472.0f);
            *reinterpret_cast<__half2*>(Eb + (size_t)mg*S + q0 + 2*lane) =
                __floats2half2_rn(e0, e1);           // coalesced 128B/warp
        }
    }
}

// ============================================================
// Kernel 2b: per-m colsum of stored E + EXACT bucketed VT:
// Vp' = V * (2^10 / colsum); buckets a:|.|<2^14, b:[2^14,2^29)*2^-15,
// c:>=2^29 *2^-30 (disjoint: each value exact in one bucket).
// One warp per m-row, coalesced uint4 E loads. grid BH*S/8, 256 thr.
// ============================================================
__global__ void __launch_bounds__(256) colsumVp3_kernel() {
    const int w = threadIdx.x >> 5, lane = threadIdx.x & 31;
    const size_t row = (size_t)blockIdx.x*8 + w;       // bh*S + m
    const __half* Er = g_E + row*S;
    float s = 0.f;
    #pragma unroll
    for (int i = 0; i < 8; i++) {
        uint4 u = *reinterpret_cast<const uint4*>(Er + i*256 + lane*8);
        float2 f0 = __half22float2(*reinterpret_cast<__half2*>(&u.x));
        float2 f1 = __half22float2(*reinterpret_cast<__half2*>(&u.y));
        float2 f2 = __half22float2(*reinterpret_cast<__half2*>(&u.z));
        float2 f3 = __half22float2(*reinterpret_cast<__half2*>(&u.w));
        s += (f0.x + f0.y) + (f1.x + f1.y) + (f2.x + f2.y) + (f3.x + f3.y);
    }
    #pragma unroll
    for (int off = 16; off; off >>= 1)
        s += __shfl_xor_sync(0xffffffffu, s, off);
    const float rc = (s > 0.f) ? __frcp_rn(s) * 1024.0f : 0.f;
    if (lane < DK) {
        const int bh = (int)(row >> 11), m = (int)(row & (S-1));
        const float vp = g_V[row*DK + lane] * rc;
        const float av = fabsf(vp);
        const float a = (av < 16384.0f) ? vp : 0.f;
        const float b = (av >= 16384.0f && av < 536870912.0f)
                            ? vp * (1.0f/32768.0f) : 0.f;
        const float c = (av >= 536870912.0f) ? vp * (1.0f/1073741824.0f) : 0.f;
        const size_t o = (size_t)bh*DK*S + (size_t)lane*S + m;
        g_VTa[o] = __float2half(a);
        g_VTb[o] = __float2half(b);
        g_VTc[o] = __float2half(c);
    }
}

// ============================================================
// Kernel 3: out = E^T @ Vp via HMMA m16n8k16, 3 range buckets.
// grid (S/64, BH), 128 threads. Warp w owns q rows [q0+16w, +16).
// E tiles staged in SMEM (144B row stride: conflict-free ldmatrix);
// B fragments are contiguous u32 loads (L2-hot). Epilogue combines
// (Ca + 2^15 Cb + 2^30 Cc) * 2^-10.
// ============================================================
__global__ void __launch_bounds__(128) ev_kernel() {
    __shared__ __align__(16) char Es[64*144];
    const int t = threadIdx.x, w = t >> 5, lane = t & 31;
    const int bh = blockIdx.y, q0 = blockIdx.x * 64;
    const __half* Eb = g_E + (size_t)bh*S*S;
    const size_t bt0 = (size_t)bh*DK*S;
    const int g = lane >> 2, tq = lane & 3;
    const int lrow  = (lane & 7) + ((lane >> 4) << 3);
    const int lqoff = ((lane >> 3) & 1)*16 + w*32;
    const u32 es0 = smem_u32(Es);

    float accA[8] = {}, accB[8] = {}, accC[8] = {};

    for (int m0 = 0; m0 < S; m0 += 64) {
        __syncthreads();
        #pragma unroll
        for (int pp = 0; pp < 4; pp++) {            // stage 64x64 E tile
            int idx = t + pp*128;
            int r = idx >> 3, pc = idx & 7;
            *reinterpret_cast<uint4*>(Es + r*144 + pc*16) =
                *reinterpret_cast<const uint4*>(Eb + (size_t)(m0 + r)*S + q0 + pc*8);
        }
        __syncthreads();

        #pragma unroll
        for (int ck = 0; ck < 4; ck++) {            // 4 k-steps of 16 m
            u32 a0, a1, a2, a3;
            u32 addr = es0 + (ck*16 + lrow)*144 + lqoff;
            asm volatile(
                "ldmatrix.sync.aligned.m8n8.x4.trans.shared.b16 {%0,%1,%2,%3}, [%4];"
                : "=r"(a0), "=r"(a1), "=r"(a2), "=r"(a3) : "r"(addr));
            const int mk = m0 + ck*16;
            const size_t i00 = bt0 + (size_t)g*S     + mk + 2*tq;
            const size_t i10 = bt0 + (size_t)(g+8)*S + mk + 2*tq;

            #pragma unroll
            for (int bk = 0; bk < 3; bk++) {
                const __half* Bt = (bk == 0) ? g_VTa : (bk == 1) ? g_VTb : g_VTc;
                float* acc = (bk == 0) ? accA : (bk == 1) ? accB : accC;
                u32 b00 = *reinterpret_cast<const u32*>(Bt + i00);
                u32 b01 = *reinterpret_cast<const u32*>(Bt + i00 + 8);
                u32 b10 = *reinterpret_cast<const u32*>(Bt + i10);
                u32 b11 = *reinterpret_cast<const u32*>(Bt + i10 + 8);
                asm volatile(
                    "mma.sync.aligned.m16n8k16.row.col.f32.f16.f16.f32 "
                    "{%0,%1,%2,%3}, {%4,%5,%6,%7}, {%8,%9}, {%0,%1,%2,%3};"
                    : "+f"(acc[0]), "+f"(acc[1]), "+f"(acc[2]), "+f"(acc[3])
                    : "r"(a0), "r"(a1), "r"(a2), "r"(a3), "r"(b00), "r"(b01));
                asm volatile(
                    "mma.sync.aligned.m16n8k16.row.col.f32.f16.f16.f32 "
                    "{%0,%1,%2,%3}, {%4,%5,%6,%7}, {%8,%9}, {%0,%1,%2,%3};"
                    : "+f"(acc[4]), "+f"(acc[5]), "+f"(acc[6]), "+f"(acc[7])
                    : "r"(a0), "r"(a1), "r"(a2), "r"(a3), "r"(b10), "r"(b11));
            }
        }
    }

    const int b = bh >> 3, h = bh & 7;
    float o[8];
    #pragma unroll
    for (int i = 0; i < 8; i++)
        o[i] = (accA[i] + 32768.0f*accB[i] + 1073741824.0f*accC[i])
               * (1.0f/1024.0f);
    const int q = q0 + w*16 + g;
    float* d0 = g_head + (b*S + q)*D     + h*DK;
    float* d1 = g_head + (b*S + q + 8)*D + h*DK;
    *reinterpret_cast<float2*>(d0 + 2*tq)     = make_float2(o[0], o[1]);
    *reinterpret_cast<float2*>(d0 + 8 + 2*tq) = make_float2(o[4], o[5]);
    *reinterpret_cast<float2*>(d1 + 2*tq)     = make_float2(o[2], o[3]);
    *reinterpret_cast<float2*>(d1 + 8 + 2*tq) = make_float2(o[6], o[7]);
}

// ============================================================
// Kernel 4: out = head[B*S,128] @ w_o[128,128]. grid 256, 256 thr.
// ============================================================
__global__ void final_proj_kernel(const float* __restrict__ wo,
                                  float* __restrict__ out) {
    __shared__ float hsT[128][34];
    const int t = threadIdx.x;
    const int row0 = blockIdx.x * 32;

    #pragma unroll
    for (int k = 0; k < 4; k++) {
        int idx = t + k*256;
        int r = idx >> 5, j4 = idx & 31;
        float4 v = *reinterpret_cast<const float4*>(g_head + (row0 + r)*D + j4*4);
        hsT[j4*4+0][r] = v.x; hsT[j4*4+1][r] = v.y;
        hsT[j4*4+2][r] = v.z; hsT[j4*4+3][r] = v.w;
    }
    __syncthreads();

    const int c = t & 127, rh = t >> 7;
    u64 acc[8] = {};
    #pragma unroll 4
    for (int j = 0; j < D; j++) {
        u64 w = dup2(wo[j*D + c]);
        #pragma unroll
        for (int p = 0; p < 8; p++)
            ffma2(acc[p], lds64(&hsT[j][rh*16 + 2*p]), w);
    }
    #pragma unroll
    for (int p = 0; p < 8; p++) {
        float2 v = unpk(acc[p]);
        int r = row0 + rh*16 + 2*p;
        out[r*D + c]     = v.x;
        out[(r+1)*D + c] = v.y;
    }
}

// ============================================================
extern "C" void kernel_launch(void* const* d_in, const int* in_sizes, int n_in,
                              void* d_out, int out_size) {
    const float* x  = (const float*)d_in[0];
    const float* wq = (const float*)d_in[1];
    const float* wk = (const float*)d_in[2];
    const float* wv = (const float*)d_in[3];
    const float* wo = (const float*)d_in[4];
    float* out = (float*)d_out;

    proj_kernel      <<< dim3(Bsz*S/64, 3), 128 >>>(x, wq, wk, wv);
    qnorm_kernel     <<< BH,                256 >>>();
    scoresE_kernel   <<< dim3(S/64, BH),    128 >>>();
    colsumVp3_kernel <<< BH*S/8,            256 >>>();
    ev_kernel        <<< dim3(S/64, BH),    128 >>>();
    final_proj_kernel<<< Bsz*S/32,          256 >>>(wo, out);
}

// round 13
// speedup vs baseline: 1.2312x; 1.0739x over previous
#include <cuda_runtime.h>
#include <cuda_fp16.h>

#define Bsz 4
#define S   2048
#define D   128
#define H   8
#define DK  16
#define BH  (Bsz*H)
#define NQT (S/64)

typedef unsigned long long u64;
typedef unsigned int u32;

// 0.25 * log2(e): folded into Q at projection time so attention uses raw ex2
#define SCQ 0.36067376022224086f

// ---- scratch (no device allocations allowed) ----
__device__ float g_Q[BH*S*DK];                // pre-scaled by SCQ
__device__ float g_K[BH*S*DK];
__device__ float g_V[BH*S*DK];
__device__ __half g_E[(size_t)BH*S*S];        // 256 MB, [bh][m][q], per-column biased
__device__ float g_colpart[NQT*BH*S];         // per-q-tile colsum partials (8 MB)
__device__ __half g_VTa[BH*DK*S];             // bucketed (V*rc*2^10)^T, |.|<2^14
__device__ __half g_VTb[BH*DK*S];             // [2^14,2^29) stored *2^-15
__device__ __half g_VTc[BH*DK*S];             // >=2^29 stored *2^-30
__device__ float g_maxqn[BH];                 // max ||Qhat|| per head
__device__ float g_head[Bsz*S*D];

// ---- packed fp32x2 helpers ----
__device__ __forceinline__ void ffma2(u64& d, u64 a, u64 b){
    asm("fma.rn.f32x2 %0, %1, %2, %0;" : "+l"(d) : "l"(a), "l"(b));
}
__device__ __forceinline__ u64 add2(u64 a, u64 b){
    u64 r; asm("add.rn.f32x2 %0, %1, %2;" : "=l"(r) : "l"(a), "l"(b)); return r;
}
__device__ __forceinline__ u64 pack2(float lo, float hi){
    u64 r; asm("mov.b64 %0, {%1, %2};" : "=l"(r) : "f"(lo), "f"(hi)); return r;
}
__device__ __forceinline__ u64 dup2(float x){
    u64 r; asm("mov.b64 %0, {%1, %1};" : "=l"(r) : "f"(x)); return r;
}
__device__ __forceinline__ float hsum2(u64 v){
    float lo, hi; asm("mov.b64 {%0, %1}, %2;" : "=f"(lo), "=f"(hi) : "l"(v));
    return lo + hi;
}
__device__ __forceinline__ float2 unpk(u64 v){
    float2 r; asm("mov.b64 {%0, %1}, %2;" : "=f"(r.x), "=f"(r.y) : "l"(v));
    return r;
}
__device__ __forceinline__ float ex2f(float x){
    float r; asm("ex2.approx.f32 %0, %1;" : "=f"(r) : "f"(x)); return r;
}
__device__ __forceinline__ u64 lds64(const float* p){
    return *reinterpret_cast<const u64*>(p);
}
__device__ __forceinline__ u64 ldg64(const float* p){
    return *reinterpret_cast<const u64*>(p);
}
__device__ __forceinline__ u32 smem_u32(const void* p){
    u32 a;
    asm("{ .reg .u64 t; cvta.to.shared.u64 t, %1; cvt.u32.u64 %0, t; }"
        : "=r"(a) : "l"(p));
    return a;
}

// ============================================================
// Kernel 1: Q/K/V projections. grid (B*S/64, 3), 128 threads.
// ============================================================
__global__ void proj_kernel(const float* __restrict__ x,
                            const float* __restrict__ wq,
                            const float* __restrict__ wk,
                            const float* __restrict__ wv) {
    __shared__ float xs[64][132];
    __shared__ float wsT[16][132];
    const int t = threadIdx.x;       // 128
    const int row0 = blockIdx.x * 64;
    const int pj = blockIdx.y;
    const float* W0 = (pj == 0 ? wq : pj == 1 ? wk : wv);
    float* dst = (pj == 0 ? g_Q : pj == 1 ? g_K : g_V);
    const float oscale = (pj == 0) ? SCQ : 1.0f;

    #pragma unroll
    for (int k = 0; k < 16; k++) {
        int idx = t + k*128;
        int r = idx >> 5, q4 = idx & 31;
        *reinterpret_cast<float4*>(&xs[r][q4*4]) =
            *reinterpret_cast<const float4*>(x + (row0 + r)*D + q4*4);
    }

    const int rg = t >> 3, cg = t & 7;
    for (int h = 0; h < H; h++) {
        __syncthreads();
        #pragma unroll
        for (int k = 0; k < 4; k++) {
            int idx = t + k*128;
            int d = idx >> 2, c4 = idx & 3;
            float4 v = *reinterpret_cast<const float4*>(W0 + h*D*DK + d*DK + c4*4);
            wsT[c4*4+0][d] = v.x; wsT[c4*4+1][d] = v.y;
            wsT[c4*4+2][d] = v.z; wsT[c4*4+3][d] = v.w;
        }
        __syncthreads();

        u64 acc[4][2] = {};
        #pragma unroll 8
        for (int d = 0; d < D; d += 2) {
            u64 w0 = lds64(&wsT[cg][d]);
            u64 w1 = lds64(&wsT[cg+8][d]);
            #pragma unroll
            for (int i = 0; i < 4; i++) {
                u64 xv = lds64(&xs[rg*4+i][d]);
                ffma2(acc[i][0], xv, w0);
                ffma2(acc[i][1], xv, w1);
            }
        }
        #pragma unroll
        for (int i = 0; i < 4; i++) {
            int grow = row0 + rg*4 + i;
            int b = grow >> 11, s = grow & (S-1);
            float* o = dst + ((b*H + h)*S + s)*DK;
            o[cg]   = hsum2(acc[i][0]) * oscale;
            o[cg+8] = hsum2(acc[i][1]) * oscale;
        }
    }
}

// ============================================================
// Kernel 1b: maxQnorm[bh] = max_q ||Qhat[q]||. grid BH, 256 threads.
// ============================================================
__global__ void __launch_bounds__(256) qnorm_kernel() {
    __shared__ float red[256];
    const int bh = blockIdx.x, t = threadIdx.x;
    const float* Qb = g_Q + bh*S*DK;
    float mx = 0.f;
    for (int r = t; r < S; r += 256) {
        u64 a = 0;
        #pragma unroll
        for (int j = 0; j < 8; j++) {
            u64 q = ldg64(Qb + r*DK + 2*j);
            ffma2(a, q, q);
        }
        mx = fmaxf(mx, hsum2(a));
    }
    red[t] = mx;
    __syncthreads();
    #pragma unroll
    for (int s2 = 128; s2; s2 >>= 1) {
        if (t < s2) red[t] = fmaxf(red[t], red[t + s2]);
        __syncthreads();
    }
    if (t == 0) g_maxqn[bh] = sqrtf(red[0]);
}

// ============================================================
// Kernel 2: E[m][q] = 2^(Qhat[q].K[m] - b_m) fp16 with CS bias
// b_m = maxQn*||K[m]|| - 8 (overflow impossible) + in-warp
// butterfly colsum partials (R5-proven, saves a full E re-read).
// grid (S/64, BH), 128 threads; lane = q-pair, warps split m.
// ============================================================
__global__ void __launch_bounds__(128) scoresE_kernel() {
    __shared__ float Ks[128][16];
    __shared__ float bs[128];
    const int t = threadIdx.x, w = t >> 5, lane = t & 31;
    const int bh = blockIdx.y;
    const int q0 = blockIdx.x * 64;
    const float* Qb = g_Q + bh*S*DK;
    const float* Kb = g_K + bh*S*DK;
    __half* Eb = g_E + (size_t)bh*S*S;
    float* cp = g_colpart + blockIdx.x*(BH*S) + bh*S;
    const float mq = g_maxqn[bh];

    u64 qa[8], qc[8];
    #pragma unroll
    for (int j = 0; j < 8; j++) {
        qa[j] = ldg64(Qb + (q0 + 2*lane)*DK + 2*j);
        qc[j] = ldg64(Qb + (q0 + 2*lane + 1)*DK + 2*j);
    }

    for (int m0 = 0; m0 < S; m0 += 128) {
        __syncthreads();                       // Ks/bs reuse
        #pragma unroll
        for (int i = 0; i < 4; i++) {
            int idx = t + i*128;
            int r = idx >> 2, c4 = idx & 3;
            *reinterpret_cast<float4*>(&Ks[r][c4*4]) =
                *reinterpret_cast<const float4*>(Kb + (m0 + r)*DK + c4*4);
        }
        __syncthreads();
        {   // per-row CS bias from SMEM (1 row per thread)
            const ulonglong2* kp = reinterpret_cast<const ulonglong2*>(&Ks[t][0]);
            u64 a = 0;
            #pragma unroll
            for (int p = 0; p < 4; p++) {
                ulonglong2 kv = kp[p];
                ffma2(a, kv.x, kv.x);
                ffma2(a, kv.y, kv.y);
            }
            bs[t] = fmaf(sqrtf(hsum2(a)), mq, -8.0f);
        }
        __syncthreads();

        const int mbase = w * 32;
        #pragma unroll 4
        for (int mi = 0; mi < 32; mi++) {
            const int m  = mbase + mi;
            const int mg = m0 + m;
            const u64 bias = pack2(-bs[m], 0.0f);
            const ulonglong2* kp = reinterpret_cast<const ulonglong2*>(&Ks[m][0]);
            u64 a0 = bias, a1 = 0, a2 = bias, a3 = 0;
            #pragma unroll
            for (int p = 0; p < 4; p++) {
                ulonglong2 kv = kp[p];               // LDS.128 broadcast
                ffma2(a0, qa[2*p],   kv.x);
                ffma2(a1, qa[2*p+1], kv.y);
                ffma2(a2, qc[2*p],   kv.x);
                ffma2(a3, qc[2*p+1], kv.y);
            }
            float e0 = fminf(ex2f(hsum2(add2(a0, a1))), 65472.0f);
            float e1 = fminf(ex2f(hsum2(add2(a2, a3))), 65472.0f);
            *reinterpret_cast<__half2*>(Eb + (size_t)mg*S + q0 + 2*lane) =
                __floats2half2_rn(e0, e1);           // coalesced 128B/warp
            // partial colsum over this CTA's 64 q's
            float cs = e0 + e1;
            #pragma unroll
            for (int off = 16; off; off >>= 1)
                cs += __shfl_xor_sync(0xffffffffu, cs, off);
            if (lane == 0) cp[mg] = cs;
        }
    }
}

// ============================================================
// Kernel 2b: reduce colsum partials + EXACT bucketed VT:
// Vp' = V * (2^10 / colsum); buckets a:|.|<2^14, b:[2^14,2^29)*2^-15,
// c:>=2^29 *2^-30 (disjoint, each value exact in one bucket).
// grid BH*S/256, 256 threads, 1 m-row each. ~20 MB total traffic.
// ============================================================
__global__ void __launch_bounds__(256) colredVp3_kernel() {
    const int row = blockIdx.x*256 + threadIdx.x;   // bh*S + m
    float s = 0.f;
    #pragma unroll
    for (int qt = 0; qt < NQT; qt++) s += g_colpart[qt*(BH*S) + row];
    const float rc = (s > 0.f) ? __frcp_rn(s) * 1024.0f : 0.f;
    const int bh = row >> 11, m = row & (S-1);
    const float* Vr = g_V + row*DK;
    #pragma unroll
    for (int v = 0; v < DK; v++) {
        const float vp = Vr[v] * rc;
        const float av = fabsf(vp);
        const float a = (av < 16384.0f) ? vp : 0.f;
        const float b = (av >= 16384.0f && av < 536870912.0f)
                            ? vp * (1.0f/32768.0f) : 0.f;
        const float c = (av >= 536870912.0f) ? vp * (1.0f/1073741824.0f) : 0.f;
        const size_t o = (size_t)bh*DK*S + (size_t)v*S + m;
        g_VTa[o] = __float2half(a);
        g_VTb[o] = __float2half(b);
        g_VTc[o] = __float2half(c);
    }
}

// ============================================================
// Kernel 3: out = E^T @ Vp via HMMA m16n8k16, 3 range buckets.
// grid (S/128, BH), 128 threads. q-tile 128: warp w owns 32 q
// (2 m16 subtiles) -> B fragments loaded ONCE per ck per warp and
// reused across subtiles (R12's 4x-redundant B traffic halved again).
// E tiles 64m x 128q staged in SMEM (272B row stride, conflict-free
// ldmatrix). Epilogue combines (Ca + 2^15 Cb + 2^30 Cc) * 2^-10.
// ============================================================
__global__ void __launch_bounds__(128) ev_kernel() {
    __shared__ __align__(16) char Es[64*272];       // 64 m x 128 q fp16, padded
    const int t = threadIdx.x, w = t >> 5, lane = t & 31;
    const int bh = blockIdx.y, q0 = blockIdx.x * 128;
    const __half* Eb = g_E + (size_t)bh*S*S;
    const size_t bt0 = (size_t)bh*DK*S;
    const int g = lane >> 2, tq = lane & 3;
    const int lrow   = (lane & 7) + ((lane >> 4) << 3);
    const int lqbase = 64*w + ((lane >> 3) & 1)*16;   // bytes within row
    const u32 es0 = smem_u32(Es);

    float acc[2][3][8] = {};                     // [subtile][bucket][frag]

    for (int m0 = 0; m0 < S; m0 += 64) {
        __syncthreads();
        #pragma unroll
        for (int pp = 0; pp < 8; pp++) {         // stage 64x128 E tile (16KB)
            int idx = t + pp*128;
            int r = idx >> 4, pc = idx & 15;
            *reinterpret_cast<uint4*>(Es + r*272 + pc*16) =
                *reinterpret_cast<const uint4*>(Eb + (size_t)(m0 + r)*S + q0 + pc*8);
        }
        __syncthreads();

        #pragma unroll
        for (int ck = 0; ck < 4; ck++) {         // 4 k-steps of 16 m
            const int mk = m0 + ck*16;
            const size_t i00 = bt0 + (size_t)g*S     + mk + 2*tq;
            const size_t i10 = bt0 + (size_t)(g+8)*S + mk + 2*tq;
            // B fragments: once per ck, reused for both subtiles
            u32 B[3][4];
            #pragma unroll
            for (int bk = 0; bk < 3; bk++) {
                const __half* Bt = (bk == 0) ? g_VTa : (bk == 1) ? g_VTb : g_VTc;
                B[bk][0] = *reinterpret_cast<const u32*>(Bt + i00);
                B[bk][1] = *reinterpret_cast<const u32*>(Bt + i00 + 8);
                B[bk][2] = *reinterpret_cast<const u32*>(Bt + i10);
                B[bk][3] = *reinterpret_cast<const u32*>(Bt + i10 + 8);
            }
            #pragma unroll
            for (int s = 0; s < 2; s++) {
                u32 a0, a1, a2, a3;
                u32 addr = es0 + (ck*16 + lrow)*272 + lqbase + 32*s;
                asm volatile(
                    "ldmatrix.sync.aligned.m8n8.x4.trans.shared.b16 {%0,%1,%2,%3}, [%4];"
                    : "=r"(a0), "=r"(a1), "=r"(a2), "=r"(a3) : "r"(addr));
                #pragma unroll
                for (int bk = 0; bk < 3; bk++) {
                    float* ac = acc[s][bk];
                    asm volatile(
                        "mma.sync.aligned.m16n8k16.row.col.f32.f16.f16.f32 "
                        "{%0,%1,%2,%3}, {%4,%5,%6,%7}, {%8,%9}, {%0,%1,%2,%3};"
                        : "+f"(ac[0]), "+f"(ac[1]), "+f"(ac[2]), "+f"(ac[3])
                        : "r"(a0), "r"(a1), "r"(a2), "r"(a3),
                          "r"(B[bk][0]), "r"(B[bk][1]));
                    asm volatile(
                        "mma.sync.aligned.m16n8k16.row.col.f32.f16.f16.f32 "
                        "{%0,%1,%2,%3}, {%4,%5,%6,%7}, {%8,%9}, {%0,%1,%2,%3};"
                        : "+f"(ac[4]), "+f"(ac[5]), "+f"(ac[6]), "+f"(ac[7])
                        : "r"(a0), "r"(a1), "r"(a2), "r"(a3),
                          "r"(B[bk][2]), "r"(B[bk][3]));
                }
            }
        }
    }

    const int b = bh >> 3, h = bh & 7;
    #pragma unroll
    for (int s = 0; s < 2; s++) {
        float o[8];
        #pragma unroll
        for (int i = 0; i < 8; i++)
            o[i] = (acc[s][0][i] + 32768.0f*acc[s][1][i]
                    + 1073741824.0f*acc[s][2][i]) * (1.0f/1024.0f);
        const int q = q0 + 32*w + 16*s + g;
        float* d0 = g_head + (b*S + q)*D     + h*DK;
        float* d1 = g_head + (b*S + q + 8)*D + h*DK;
        *reinterpret_cast<float2*>(d0 + 2*tq)     = make_float2(o[0], o[1]);
        *reinterpret_cast<float2*>(d0 + 8 + 2*tq) = make_float2(o[4], o[5]);
        *reinterpret_cast<float2*>(d1 + 2*tq)     = make_float2(o[2], o[3]);
        *reinterpret_cast<float2*>(d1 + 8 + 2*tq) = make_float2(o[6], o[7]);
    }
}

// ============================================================
// Kernel 4: out = head[B*S,128] @ w_o[128,128]. grid 256, 256 thr.
// ============================================================
__global__ void final_proj_kernel(const float* __restrict__ wo,
                                  float* __restrict__ out) {
    __shared__ float hsT[128][34];
    const int t = threadIdx.x;
    const int row0 = blockIdx.x * 32;

    #pragma unroll
    for (int k = 0; k < 4; k++) {
        int idx = t + k*256;
        int r = idx >> 5, j4 = idx & 31;
        float4 v = *reinterpret_cast<const float4*>(g_head + (row0 + r)*D + j4*4);
        hsT[j4*4+0][r] = v.x; hsT[j4*4+1][r] = v.y;
        hsT[j4*4+2][r] = v.z; hsT[j4*4+3][r] = v.w;
    }
    __syncthreads();

    const int c = t & 127, rh = t >> 7;
    u64 acc[8] = {};
    #pragma unroll 4
    for (int j = 0; j < D; j++) {
        u64 w = dup2(wo[j*D + c]);
        #pragma unroll
        for (int p = 0; p < 8; p++)
            ffma2(acc[p], lds64(&hsT[j][rh*16 + 2*p]), w);
    }
    #pragma unroll
    for (int p = 0; p < 8; p++) {
        float2 v = unpk(acc[p]);
        int r = row0 + rh*16 + 2*p;
        out[r*D + c]     = v.x;
        out[(r+1)*D + c] = v.y;
    }
}

// ============================================================
extern "C" void kernel_launch(void* const* d_in, const int* in_sizes, int n_in,
                              void* d_out, int out_size) {
    const float* x  = (const float*)d_in[0];
    const float* wq = (const float*)d_in[1];
    const float* wk = (const float*)d_in[2];
    const float* wv = (const float*)d_in[3];
    const float* wo = (const float*)d_in[4];
    float* out = (float*)d_out;

    proj_kernel      <<< dim3(Bsz*S/64, 3), 128 >>>(x, wq, wk, wv);
    qnorm_kernel     <<< BH,                256 >>>();
    scoresE_kernel   <<< dim3(S/64, BH),    128 >>>();
    colredVp3_kernel <<< BH*S/256,          256 >>>();
    ev_kernel        <<< dim3(S/128, BH),   128 >>>();
    final_proj_kernel<<< Bsz*S/32,          256 >>>(wo, out);
}